// round 15
// baseline (speedup 1.0000x reference)
#include <cuda_runtime.h>
#include <cuda_fp16.h>
#include <cstdint>

// ---------------- problem constants ----------------
#define NODES   262144
#define BGRAPH  1024
#define NPG     256
#define HID     192
#define HID2    384
#define NEDGE   4194304
#define KKEEP   231
#define LN_EPS  1e-5f

// exact power-of-2 scaling keeps all fp16 split terms in normal range
#define XSCALE  256.0f          // A pre-scale (2^8)
#define WSCALE  2048.0f         // B pre-scale (2^11)
#define DESCALE (1.0f / 524288.0f)   // 2^-19

// ---------------- head tiling ----------------
#define MTILE   64             // nodes per CTA (head)
#define NB      (NODES / MTILE) // 4096 node blocks
#define KSTEPS  12             // K = 192 in chunks of 16
#define NTHREAD 256            // 8 warps: 2 (M) x 4 (N), warp tile 32 x 96

// B in mma-fragment layout: [ks 12][wc 4][sbp 2][p 6][lane 32][reg 4] u32
__device__ __align__(16) uint32_t d_Bfrag[147456];
// A in mma-fragment layout: [nb 4096][grp 4][split 2][ks 12][lane 32] uint4
//   grp = 16-row group within the 64-node block (grp = wr*2 + m)
__device__ __align__(16) uint4 d_Afrag[12582912];   // 201 MB
__device__ float2        d_klg[NODES];      // {keep, logit} packed
__device__ unsigned char d_touched[NODES];

// ---------------- asplit (128 rows/CTA, 512 threads) ----------------
#define AS_ROWS   128
#define NBA       (NODES / AS_ROWS)      // 2048 CTAs
#define A_PITCH   200                    // fp16/row (odd multiple of 8 -> ldsm conflict-free)
#define AS_SPLIT_B (AS_ROWS * A_PITCH * 2)   // 51200 per split
#define ASPLIT_SMEM (2 * AS_SPLIT_B)         // 102400

// ---------------- PTX helpers (sm_80-era, safe for compute_103) ----------
__device__ __forceinline__ uint32_t smem_u32(const void* p) {
    uint32_t a;
    asm("{ .reg .u64 t; cvta.to.shared.u64 t, %1; cvt.u32.u64 %0, t; }"
        : "=r"(a) : "l"(p));
    return a;
}
__device__ __forceinline__ void ldsm4(uint32_t* r, uint32_t a) {
    asm volatile("ldmatrix.sync.aligned.m8n8.x4.shared.b16 {%0,%1,%2,%3}, [%4];"
                 : "=r"(r[0]), "=r"(r[1]), "=r"(r[2]), "=r"(r[3]) : "r"(a));
}
__device__ __forceinline__ void mma16816(float* d, const uint32_t* a, const uint32_t* b) {
    asm volatile("mma.sync.aligned.m16n8k16.row.col.f32.f16.f16.f32 "
                 "{%0,%1,%2,%3}, {%4,%5,%6,%7}, {%8,%9}, {%0,%1,%2,%3};"
                 : "+f"(d[0]), "+f"(d[1]), "+f"(d[2]), "+f"(d[3])
                 : "r"(a[0]), "r"(a[1]), "r"(a[2]), "r"(a[3]),
                   "r"(b[0]), "r"(b[1]));
}
__device__ __forceinline__ uint32_t packh(float x0, float x1) {
    return ((uint32_t)__half_as_ushort(__float2half_rn(x1)) << 16)
         | __half_as_ushort(__float2half_rn(x0));
}
__device__ __forceinline__ float resid(float x) {
    return x - __half2float(__float2half_rn(x));
}

// ---------------------------------------------------------------------------
// Prologue 1: 2-way fp16 split of W1^T * 2^11 into the m16n8k16 B fragment
// layout: reg r of lane holds B[n][k], B[n][k+1] with
//   n = wc*96 + p*16 + (r>=2 ? 8 : 0) + lane/4
//   k = ks*16 + (r&1)*8 + (lane%4)*2
// ---------------------------------------------------------------------------
__global__ void __launch_bounds__(256)
wsplit_kernel(const float* __restrict__ W1)
{
    int idx = blockIdx.x * 256 + threadIdx.x;      // 147456 = 576 * 256
    int lane_r = idx & 127;
    int lane = lane_r >> 2, r = lane_r & 3;
    int rest = idx >> 7;                           // ((ks*4+wc)*2+sbp)*6 + p
    int p = rest % 6; rest /= 6;
    int sbp = rest & 1; rest >>= 1;
    int wc = rest & 3;
    int ks = rest >> 2;

    int n = wc * 96 + p * 16 + ((r >> 1) << 3) + (lane >> 2);
    int k = ks * 16 + ((r & 1) << 3) + ((lane & 3) << 1);

    float x0 = W1[k * HID2 + n] * WSCALE;
    float x1 = W1[(k + 1) * HID2 + n] * WSCALE;
    uint32_t v;
    if (sbp == 0) v = packh(x0, x1);
    else          v = packh(resid(x0), resid(x1));
    d_Bfrag[idx] = v;
}

// ---------------------------------------------------------------------------
// Prologue 2: A build + fragment emission (decoupled from the GEMM).
// 128 rows / CTA, 512 threads. float4 loads of h and g; 2-way fp16 split
// into smem (pitch 200 halves); 16 warps = 8 row-groups x 2 splits each
// ldsm + STG.128 the fragments into d_Afrag in mma register layout.
// ---------------------------------------------------------------------------
__global__ void __launch_bounds__(512, 1)
asplit_kernel(const float* __restrict__ h, const float* __restrict__ g)
{
    extern __shared__ char sm[];
    const uint32_t sb = smem_u32(sm);
    const int tid = threadIdx.x;
    const int wid = tid >> 5;
    const int lane = tid & 31;
    const int b = blockIdx.x;            // 0..2047
    const int n0 = b * AS_ROWS;
    const int graph = n0 >> 8;           // 128 | 256 -> single graph per CTA

    // ---- A build: x = (h + g)*2^8, split -> smem (float4 path) ----
    {
        const float4* h4p = (const float4*)h;   // 48 float4 per row
        const float4* g4p = (const float4*)g;
#pragma unroll 4
        for (int i = tid; i < AS_ROWS * 48; i += 512) {
            int row = i / 48, q4 = i % 48;
            float4 hv = h4p[(n0 + row) * 48 + q4];
            float4 gv = __ldg(&g4p[graph * 48 + q4]);
            float x0 = (hv.x + gv.x) * XSCALE;
            float x1 = (hv.y + gv.y) * XSCALE;
            float x2 = (hv.z + gv.z) * XSCALE;
            float x3 = (hv.w + gv.w) * XSCALE;

            uint2 s0 = make_uint2(packh(x0, x1), packh(x2, x3));
            uint2 s1 = make_uint2(packh(resid(x0), resid(x1)),
                                  packh(resid(x2), resid(x3)));

            uint32_t off = (uint32_t)row * (A_PITCH * 2) + (uint32_t)q4 * 8u;
            *(uint2*)(sm + off)              = s0;
            *(uint2*)(sm + AS_SPLIT_B + off) = s1;
        }
    }
    __syncthreads();

    // ---- fragment emission: warp = (grp 0..7, split 0..1) ----
    const int grp = wid >> 1;            // 16-row group within 128 rows
    const int s   = wid & 1;
    const int q   = lane >> 3;
    const uint32_t addr = sb + (uint32_t)s * AS_SPLIT_B
        + (uint32_t)(grp * 16 + (lane & 7) + ((q & 1) << 3)) * (A_PITCH * 2)
        + (uint32_t)((q >> 1) << 3) * 2u;
    const int nb = b * 2 + (grp >> 2);   // head-visible 64-row block
    const int g4i = grp & 3;             // grp within that block
    uint4* dst = &d_Afrag[(uint32_t)(((nb * 4 + g4i) * 2 + s) * 12) * 32u + (uint32_t)lane];
#pragma unroll
    for (int ks = 0; ks < KSTEPS; ks++) {
        uint32_t r[4];
        ldsm4(r, addr + (uint32_t)ks * 32u);
        dst[ks * 32] = make_uint4(r[0], r[1], r[2], r[3]);
    }
}

// no-op launch: keep head_kernel at captured launch slot #4 for ncu
__global__ void dummy_kernel() {}

// ---------------------------------------------------------------------------
// Fragment loads (all straight to registers, coalesced LDG.128)
// ---------------------------------------------------------------------------
__device__ __forceinline__ void loadA(uint4* dst, int nb, int wr, int ks, int lane) {
#pragma unroll
    for (int m = 0; m < 2; m++)
#pragma unroll
        for (int s = 0; s < 2; s++)
            dst[m * 2 + s] = __ldg(&d_Afrag[
                (uint32_t)((((nb * 4 + wr * 2 + m) * 2 + s) * 12 + ks)) * 32u
                + (uint32_t)lane]);
}
__device__ __forceinline__ void loadB0(uint4* dst, int ks, uint32_t wbase) {
    const uint4* __restrict__ B4 = (const uint4*)d_Bfrag;
#pragma unroll
    for (int j = 0; j < 6; j++)
        dst[j] = __ldg(&B4[(uint32_t)ks * 1536u + wbase + (uint32_t)j * 32u]);
}

// One k-step: JIT-load B split1, then 72 MMAs (3 terms).
__device__ __forceinline__ void doKstep(float acc[2][12][4], const uint4* Av,
                                        const uint4* B0, int ks, uint32_t wbase) {
    const uint4* __restrict__ B4 = (const uint4*)d_Bfrag;
    uint4 Bs1[6];
#pragma unroll
    for (int j = 0; j < 6; j++)      // issue early; covered by 48 MMAs below
        Bs1[j] = __ldg(&B4[(uint32_t)ks * 1536u + wbase + 192u + (uint32_t)j * 32u]);

    // b-split 0: terms a1b1 (sa=0) and a2b1 (sa=1)
#pragma unroll
    for (int sa = 0; sa < 2; sa++)
#pragma unroll
        for (int p = 0; p < 6; p++) {
            const uint32_t* b = (const uint32_t*)&B0[p];
#pragma unroll
            for (int m = 0; m < 2; m++) {
                const uint32_t* a = (const uint32_t*)&Av[m * 2 + sa];
                mma16816(acc[m][2 * p],     a, b);
                mma16816(acc[m][2 * p + 1], a, b + 2);
            }
        }
    // b-split 1: term a1b2 (a2b2 dropped, ~1e-8 rel; validated R10/R11/R13/R14)
#pragma unroll
    for (int p = 0; p < 6; p++) {
        const uint32_t* b = (const uint32_t*)&Bs1[p];
#pragma unroll
        for (int m = 0; m < 2; m++) {
            const uint32_t* a = (const uint32_t*)&Av[m * 2];
            mma16816(acc[m][2 * p],     a, b);
            mma16816(acc[m][2 * p + 1], a, b + 2);
        }
    }
}

// ---------------------------------------------------------------------------
// Head GEMM: 64 nodes x 384 cols per CTA; 8 warps (2 M x 4 N), tile 32x96.
// Pure LDG+HMMA mainloop. A TRIPLE-buffered (prefetch 2 k-steps ahead) to
// cover DRAM latency (~600-1000 cyc) that a 1-step buffer (~520 cyc of MMA)
// left exposed. B double-buffered (L2-resident, 1 step suffices).
// ---------------------------------------------------------------------------
__global__ void __launch_bounds__(NTHREAD, 1)
head_kernel(const float* __restrict__ b1, const float* __restrict__ lngamma,
            const float* __restrict__ lnbeta, const float* __restrict__ W2,
            const float* __restrict__ b2, float* __restrict__ logits)
{
    __shared__ float par[4 * HID2];
    __shared__ float rs1[MTILE * 4], rs2[MTILE * 4], rt[MTILE * 4];

    const int tid  = threadIdx.x;
    const int wid  = tid >> 5;
    const int lane = tid & 31;
    const int wr   = wid & 1;            // M-warp (2), 32 rows each
    const int wc   = wid >> 1;           // N-warp (4), 96 cols each
    const int nb   = blockIdx.x;
    const int n0   = nb * MTILE;
    const float b2v = __ldg(b2);

    for (int i = tid; i < HID2; i += NTHREAD) {
        par[i]            = b1[i];
        par[HID2 + i]     = lngamma[i];
        par[2 * HID2 + i] = lnbeta[i];
        par[3 * HID2 + i] = W2[i];
    }
    __syncthreads();

    const uint32_t wbase = (uint32_t)wc * 384u + (uint32_t)lane;

    float acc[2][12][4];
#pragma unroll
    for (int m = 0; m < 2; m++)
#pragma unroll
        for (int nt = 0; nt < 12; nt++)
#pragma unroll
            for (int j = 0; j < 4; j++) acc[m][nt][j] = 0.f;

    // ---- main loop: A triple-buffered, B-split0 double-buffered ----
    uint4 A[3][4], B[2][6];
    loadA(A[0], nb, wr, 0, lane);
    loadA(A[1], nb, wr, 1, lane);
    loadB0(B[0], 0, wbase);
#pragma unroll
    for (int ks = 0; ks < KSTEPS; ks++) {
        if (ks + 2 < KSTEPS) loadA(A[(ks + 2) % 3], nb, wr, ks + 2, lane);
        if (ks + 1 < KSTEPS) loadB0(B[(ks + 1) & 1], ks + 1, wbase);
        doKstep(acc, A[ks % 3], B[ks & 1], ks, wbase);
    }

    // ---- epilogue: descale, +b1, LN stats, LN+ReLU+dot(W2) ----
    const int l4 = lane >> 2, lm = lane & 3;

#pragma unroll
    for (int m = 0; m < 2; m++)
#pragma unroll
        for (int hf = 0; hf < 2; hf++) {
            float s1 = 0.f, s2 = 0.f;
#pragma unroll
            for (int nt = 0; nt < 12; nt++) {
                const int cb = wc * 96 + nt * 8 + 2 * lm;
                float2 bv = *(const float2*)&par[cb];
                float v0 = acc[m][nt][2 * hf]     * DESCALE + bv.x;
                float v1 = acc[m][nt][2 * hf + 1] * DESCALE + bv.y;
                s1 += v0 + v1; s2 += v0 * v0 + v1 * v1;
            }
            s1 += __shfl_xor_sync(0xffffffffu, s1, 1);
            s1 += __shfl_xor_sync(0xffffffffu, s1, 2);
            s2 += __shfl_xor_sync(0xffffffffu, s2, 1);
            s2 += __shfl_xor_sync(0xffffffffu, s2, 2);
            if (lm == 0) {
                const int row = wr * 32 + m * 16 + hf * 8 + l4;
                rs1[row * 4 + wc] = s1;
                rs2[row * 4 + wc] = s2;
            }
        }
    __syncthreads();

#pragma unroll
    for (int m = 0; m < 2; m++)
#pragma unroll
        for (int hf = 0; hf < 2; hf++) {
            const int row = wr * 32 + m * 16 + hf * 8 + l4;
            const float S1 = rs1[row * 4] + rs1[row * 4 + 1] + rs1[row * 4 + 2] + rs1[row * 4 + 3];
            const float S2 = rs2[row * 4] + rs2[row * 4 + 1] + rs2[row * 4 + 2] + rs2[row * 4 + 3];
            const float mu  = S1 * (1.0f / HID2);
            const float var = S2 * (1.0f / HID2) - mu * mu;
            const float inv = rsqrtf(var + LN_EPS);
            float t = 0.f;
#pragma unroll
            for (int nt = 0; nt < 12; nt++) {
                const int cb = wc * 96 + nt * 8 + 2 * lm;
                float2 bv = *(const float2*)&par[cb];
                float2 gm = *(const float2*)&par[HID2 + cb];
                float2 bt = *(const float2*)&par[2 * HID2 + cb];
                float2 w2 = *(const float2*)&par[3 * HID2 + cb];
                float v0 = acc[m][nt][2 * hf]     * DESCALE + bv.x;
                float v1 = acc[m][nt][2 * hf + 1] * DESCALE + bv.y;
                float z0 = fmaxf((v0 - mu) * inv * gm.x + bt.x, 0.f);
                float z1 = fmaxf((v1 - mu) * inv * gm.y + bt.y, 0.f);
                t += z0 * w2.x + z1 * w2.y;
            }
            t += __shfl_xor_sync(0xffffffffu, t, 1);
            t += __shfl_xor_sync(0xffffffffu, t, 2);
            if (lm == 0) rt[row * 4 + wc] = t;
        }
    __syncthreads();
    if (tid < MTILE)
        logits[n0 + tid] = rt[tid * 4] + rt[tid * 4 + 1] + rt[tid * 4 + 2]
                         + rt[tid * 4 + 3] + b2v;
}

// ---------------------------------------------------------------------------
// Exact per-graph top-k (jax tie semantics); writes packed {keep, logit};
// zeroes touched[].
// ---------------------------------------------------------------------------
__global__ void __launch_bounds__(256)
topk_kernel(const float* __restrict__ logits)
{
    __shared__ float sv[NPG];
    const int node = blockIdx.x * NPG + threadIdx.x;
    const int t = threadIdx.x;
    const float v = logits[node];
    sv[t] = v;
    d_touched[node] = 0;
    __syncthreads();
    int rank = 0;
#pragma unroll 8
    for (int j = 0; j < NPG; j++) {
        const float u = sv[j];
        rank += (u > v) || (u == v && j < t);
    }
    d_klg[node] = make_float2((rank < KKEEP) ? 1.0f : 0.0f, v);
}

// ---------------------------------------------------------------------------
// Edge masking + weights + touched flags (8 edges / thread for deeper MLP)
// ---------------------------------------------------------------------------
__global__ void __launch_bounds__(256)
edge_kernel(const int* __restrict__ ei,
            float* __restrict__ em, float* __restrict__ ew)
{
    const int t = blockIdx.x * 256 + threadIdx.x;    // NEDGE/8 threads
    const int4* ei4 = (const int4*)ei;
    const int4 sa = ei4[2 * t],     sb2 = ei4[2 * t + 1];
    const int4 da = ei4[NEDGE / 4 + 2 * t], db = ei4[NEDGE / 4 + 2 * t + 1];

    const float2 s0 = d_klg[sa.x], d0 = d_klg[da.x];
    const float2 s1 = d_klg[sa.y], d1 = d_klg[da.y];
    const float2 s2 = d_klg[sa.z], d2 = d_klg[da.z];
    const float2 s3 = d_klg[sa.w], d3 = d_klg[da.w];
    const float2 s4 = d_klg[sb2.x], d4 = d_klg[db.x];
    const float2 s5 = d_klg[sb2.y], d5 = d_klg[db.y];
    const float2 s6 = d_klg[sb2.z], d6 = d_klg[db.z];
    const float2 s7 = d_klg[sb2.w], d7 = d_klg[db.w];

    float4 m0, m1, w0, w1;
    m0.x = s0.x * d0.x;  w0.x = (s0.y + d0.y) * m0.x;
    m0.y = s1.x * d1.x;  w0.y = (s1.y + d1.y) * m0.y;
    m0.z = s2.x * d2.x;  w0.z = (s2.y + d2.y) * m0.z;
    m0.w = s3.x * d3.x;  w0.w = (s3.y + d3.y) * m0.w;
    m1.x = s4.x * d4.x;  w1.x = (s4.y + d4.y) * m1.x;
    m1.y = s5.x * d5.x;  w1.y = (s5.y + d5.y) * m1.y;
    m1.z = s6.x * d6.x;  w1.z = (s6.y + d6.y) * m1.z;
    m1.w = s7.x * d7.x;  w1.w = (s7.y + d7.y) * m1.w;

    ((float4*)em)[2 * t]     = m0;
    ((float4*)em)[2 * t + 1] = m1;
    ((float4*)ew)[2 * t]     = w0;
    ((float4*)ew)[2 * t + 1] = w1;

    if (m0.x != 0.f) { d_touched[sa.x] = 1; d_touched[da.x] = 1; }
    if (m0.y != 0.f) { d_touched[sa.y] = 1; d_touched[da.y] = 1; }
    if (m0.z != 0.f) { d_touched[sa.z] = 1; d_touched[da.z] = 1; }
    if (m0.w != 0.f) { d_touched[sa.w] = 1; d_touched[da.w] = 1; }
    if (m1.x != 0.f) { d_touched[sb2.x] = 1; d_touched[db.x] = 1; }
    if (m1.y != 0.f) { d_touched[sb2.y] = 1; d_touched[db.y] = 1; }
    if (m1.z != 0.f) { d_touched[sb2.z] = 1; d_touched[db.z] = 1; }
    if (m1.w != 0.f) { d_touched[sb2.w] = 1; d_touched[db.w] = 1; }
}

__global__ void __launch_bounds__(256)
mask_kernel(float* __restrict__ nm)
{
    const int i = blockIdx.x * 256 + threadIdx.x;
    nm[i] = d_touched[i] ? 1.0f : 0.0f;
}

// ---------------------------------------------------------------------------
// Launch: outputs concatenated f32: edge_mask | edge_weight | logits | node_mask
// head_kernel is launch #4 (ncu capture slot).
// ---------------------------------------------------------------------------
extern "C" void kernel_launch(void* const* d_in, const int* in_sizes, int n_in,
                              void* d_out, int out_size)
{
    const float* h       = (const float*)d_in[0];
    const float* g       = (const float*)d_in[1];
    const int*   ei      = (const int*)  d_in[2];
    const float* W1      = (const float*)d_in[3];
    const float* b1      = (const float*)d_in[4];
    const float* lngamma = (const float*)d_in[5];
    const float* lnbeta  = (const float*)d_in[6];
    const float* W2      = (const float*)d_in[7];
    const float* b2      = (const float*)d_in[8];

    float* out = (float*)d_out;
    float* em = out;
    float* ew = out + (size_t)NEDGE;
    float* lg = out + 2 * (size_t)NEDGE;
    float* nm = lg + NODES;

    cudaFuncSetAttribute(asplit_kernel,
                         cudaFuncAttributeMaxDynamicSharedMemorySize, ASPLIT_SMEM);

    wsplit_kernel<<<576, 256>>>(W1);                        // #1
    asplit_kernel<<<NBA, 512, ASPLIT_SMEM>>>(h, g);         // #2
    dummy_kernel<<<1, 32>>>();                              // #3
    head_kernel<<<NB, NTHREAD>>>(                           // #4  <- ncu slot
        b1, lngamma, lnbeta, W2, b2, lg);
    topk_kernel<<<BGRAPH, 256>>>(lg);                       // #5
    edge_kernel<<<NEDGE / 2048, 256>>>(ei, em, ew);         // #6
    mask_kernel<<<NODES / 256, 256>>>(nm);                  // #7
}

// round 17
// speedup vs baseline: 1.0981x; 1.0981x over previous
#include <cuda_runtime.h>
#include <cuda_fp16.h>
#include <cstdint>

// ---------------- problem constants ----------------
#define NODES   262144
#define BGRAPH  1024
#define NPG     256
#define HID     192
#define HID2    384
#define NEDGE   4194304
#define KKEEP   231
#define LN_EPS  1e-5f

// exact power-of-2 scaling keeps all fp16 split terms in normal range
#define XSCALE  256.0f          // A pre-scale (2^8)
#define WSCALE  2048.0f         // B pre-scale (2^11)
#define DESCALE (1.0f / 524288.0f)   // 2^-19
#define F_INF   __int_as_float(0x7f800000)

// ---------------- head tiling ----------------
#define MTILE   64             // nodes per CTA (head)
#define NB      (NODES / MTILE) // 4096 node blocks
#define KSTEPS  12             // K = 192 in chunks of 16
#define NTHREAD 256            // 8 warps: 2 (M) x 4 (N), warp tile 32 x 96

// B in mma-fragment layout: [ks 12][wc 4][sbp 2][p 6][lane 32][reg 4] u32
__device__ __align__(16) uint32_t d_Bfrag[147456];
// A in mma-fragment layout: [nb 4096][grp 4][split 2][ks 12][lane 32] uint4
__device__ __align__(16) uint4 d_Afrag[12582912];   // 201 MB
__device__ float d_kl[NODES];        // kept ? logit : +INF

// ---------------- asplit (128 rows/CTA, 512 threads) ----------------
#define AS_ROWS   128
#define NBA       (NODES / AS_ROWS)      // 2048 CTAs
#define A_PITCH   200                    // fp16/row (ldsm conflict-free)
#define AS_SPLIT_B (AS_ROWS * A_PITCH * 2)   // 51200 per split
#define ASPLIT_SMEM (2 * AS_SPLIT_B)         // 102400

// ---------------- head smem layout (dynamic) ----------------
#define STAGES      4
#define STAGE_BYTES 2048                 // 4 frag-slots * 512 (32 lanes * 16B)
#define WARP_REGION (STAGES * STAGE_BYTES)   // 8192 per warp
#define OFF_STG     0                    // 8 warps * 8192 = 65536
#define OFF_PAR     65536                // 4*384*4 = 6144
#define OFF_RS1     71680                // 1024
#define OFF_RS2     72704                // 1024
#define OFF_RT      73728                // 1024
#define HEAD_SMEM   74752

// ---------------- PTX helpers (sm_80-era, safe for compute_103) ----------
__device__ __forceinline__ uint32_t smem_u32(const void* p) {
    uint32_t a;
    asm("{ .reg .u64 t; cvta.to.shared.u64 t, %1; cvt.u32.u64 %0, t; }"
        : "=r"(a) : "l"(p));
    return a;
}
__device__ __forceinline__ void ldsm4(uint32_t* r, uint32_t a) {
    asm volatile("ldmatrix.sync.aligned.m8n8.x4.shared.b16 {%0,%1,%2,%3}, [%4];"
                 : "=r"(r[0]), "=r"(r[1]), "=r"(r[2]), "=r"(r[3]) : "r"(a));
}
__device__ __forceinline__ void lds128(uint4& v, uint32_t a) {
    asm volatile("ld.shared.v4.u32 {%0,%1,%2,%3}, [%4];"
                 : "=r"(v.x), "=r"(v.y), "=r"(v.z), "=r"(v.w) : "r"(a));
}
__device__ __forceinline__ void mma16816(float* d, const uint32_t* a, const uint32_t* b) {
    asm volatile("mma.sync.aligned.m16n8k16.row.col.f32.f16.f16.f32 "
                 "{%0,%1,%2,%3}, {%4,%5,%6,%7}, {%8,%9}, {%0,%1,%2,%3};"
                 : "+f"(d[0]), "+f"(d[1]), "+f"(d[2]), "+f"(d[3])
                 : "r"(a[0]), "r"(a[1]), "r"(a[2]), "r"(a[3]),
                   "r"(b[0]), "r"(b[1]));
}
#define CPASYNC16(dst, src) asm volatile("cp.async.cg.shared.global [%0], [%1], 16;" :: "r"(dst), "l"(src))
#define CPCOMMIT()          asm volatile("cp.async.commit_group;" ::: "memory")
#define CPWAIT(n)           asm volatile("cp.async.wait_group %0;" :: "n"(n) : "memory")

__device__ __forceinline__ uint32_t packh(float x0, float x1) {
    return ((uint32_t)__half_as_ushort(__float2half_rn(x1)) << 16)
         | __half_as_ushort(__float2half_rn(x0));
}
__device__ __forceinline__ float resid(float x) {
    return x - __half2float(__float2half_rn(x));
}

// ---------------------------------------------------------------------------
// Prologue 1: 2-way fp16 split of W1^T * 2^11 into B fragment layout.
// ---------------------------------------------------------------------------
__global__ void __launch_bounds__(256)
wsplit_kernel(const float* __restrict__ W1)
{
    int idx = blockIdx.x * 256 + threadIdx.x;      // 147456 = 576 * 256
    int lane_r = idx & 127;
    int lane = lane_r >> 2, r = lane_r & 3;
    int rest = idx >> 7;
    int p = rest % 6; rest /= 6;
    int sbp = rest & 1; rest >>= 1;
    int wc = rest & 3;
    int ks = rest >> 2;

    int n = wc * 96 + p * 16 + ((r >> 1) << 3) + (lane >> 2);
    int k = ks * 16 + ((r & 1) << 3) + ((lane & 3) << 1);

    float x0 = W1[k * HID2 + n] * WSCALE;
    float x1 = W1[(k + 1) * HID2 + n] * WSCALE;
    uint32_t v;
    if (sbp == 0) v = packh(x0, x1);
    else          v = packh(resid(x0), resid(x1));
    d_Bfrag[idx] = v;
}

// ---------------------------------------------------------------------------
// Prologue 2: A build + fragment emission (decoupled from the GEMM).
// ---------------------------------------------------------------------------
__global__ void __launch_bounds__(512, 1)
asplit_kernel(const float* __restrict__ h, const float* __restrict__ g)
{
    extern __shared__ char sm[];
    const uint32_t sb = smem_u32(sm);
    const int tid = threadIdx.x;
    const int wid = tid >> 5;
    const int lane = tid & 31;
    const int b = blockIdx.x;
    const int n0 = b * AS_ROWS;
    const int graph = n0 >> 8;

    {
        const float4* h4p = (const float4*)h;   // 48 float4 per row
        const float4* g4p = (const float4*)g;
#pragma unroll 4
        for (int i = tid; i < AS_ROWS * 48; i += 512) {
            int row = i / 48, q4 = i % 48;
            float4 hv = h4p[(n0 + row) * 48 + q4];
            float4 gv = __ldg(&g4p[graph * 48 + q4]);
            float x0 = (hv.x + gv.x) * XSCALE;
            float x1 = (hv.y + gv.y) * XSCALE;
            float x2 = (hv.z + gv.z) * XSCALE;
            float x3 = (hv.w + gv.w) * XSCALE;

            uint2 s0 = make_uint2(packh(x0, x1), packh(x2, x3));
            uint2 s1 = make_uint2(packh(resid(x0), resid(x1)),
                                  packh(resid(x2), resid(x3)));

            uint32_t off = (uint32_t)row * (A_PITCH * 2) + (uint32_t)q4 * 8u;
            *(uint2*)(sm + off)              = s0;
            *(uint2*)(sm + AS_SPLIT_B + off) = s1;
        }
    }
    __syncthreads();

    const int grp = wid >> 1;
    const int s   = wid & 1;
    const int q   = lane >> 3;
    const uint32_t addr = sb + (uint32_t)s * AS_SPLIT_B
        + (uint32_t)(grp * 16 + (lane & 7) + ((q & 1) << 3)) * (A_PITCH * 2)
        + (uint32_t)((q >> 1) << 3) * 2u;
    const int nb = b * 2 + (grp >> 2);
    const int g4i = grp & 3;
    uint4* dst = &d_Afrag[(uint32_t)(((nb * 4 + g4i) * 2 + s) * 12) * 32u + (uint32_t)lane];
#pragma unroll
    for (int ks = 0; ks < KSTEPS; ks++) {
        uint32_t r[4];
        ldsm4(r, addr + (uint32_t)ks * 32u);
        dst[ks * 32] = make_uint4(r[0], r[1], r[2], r[3]);
    }
}

// no-op launch: keep head_kernel at captured launch slot #4 for ncu
__global__ void dummy_kernel() {}

// ---------------------------------------------------------------------------
// Head helpers
// ---------------------------------------------------------------------------
// cp.async this thread's 4 A fragments for k-step ks into stage slot st.
__device__ __forceinline__ void issueA(int nb, int wr, int ks, int st,
                                       int lane, uint32_t wsm) {
    const uint32_t dst0 = wsm + (uint32_t)st * STAGE_BYTES + (uint32_t)lane * 16u;
#pragma unroll
    for (int j = 0; j < 4; j++) {      // j = m*2 + s
        const int m = j >> 1, s = j & 1;
        const uint4* src = &d_Afrag[
            (uint32_t)((((nb * 4 + wr * 2 + m) * 2 + s) * 12 + ks)) * 32u
            + (uint32_t)lane];
        CPASYNC16(dst0 + (uint32_t)j * 512u, src);
    }
}
__device__ __forceinline__ void ldsA(uint4* Afr, int st, int lane, uint32_t wsm) {
    const uint32_t a0 = wsm + (uint32_t)st * STAGE_BYTES + (uint32_t)lane * 16u;
#pragma unroll
    for (int j = 0; j < 4; j++)
        lds128(Afr[j], a0 + (uint32_t)j * 512u);
}
__device__ __forceinline__ void loadB0(uint4* dst, int ks, uint32_t wbase) {
    const uint4* __restrict__ B4 = (const uint4*)d_Bfrag;
#pragma unroll
    for (int j = 0; j < 6; j++)
        dst[j] = __ldg(&B4[(uint32_t)ks * 1536u + wbase + (uint32_t)j * 32u]);
}

// One k-step: JIT-load B split1, then 72 MMAs (3 terms).
__device__ __forceinline__ void doKstep(float acc[2][12][4], const uint4* Av,
                                        const uint4* B0, int ks, uint32_t wbase) {
    const uint4* __restrict__ B4 = (const uint4*)d_Bfrag;
    uint4 Bs1[6];
#pragma unroll
    for (int j = 0; j < 6; j++)      // issue early; covered by 48 MMAs below
        Bs1[j] = __ldg(&B4[(uint32_t)ks * 1536u + wbase + 192u + (uint32_t)j * 32u]);

    // b-split 0: terms a1b1 (sa=0) and a2b1 (sa=1)
#pragma unroll
    for (int sa = 0; sa < 2; sa++)
#pragma unroll
        for (int p = 0; p < 6; p++) {
            const uint32_t* b = (const uint32_t*)&B0[p];
#pragma unroll
            for (int m = 0; m < 2; m++) {
                const uint32_t* a = (const uint32_t*)&Av[m * 2 + sa];
                mma16816(acc[m][2 * p],     a, b);
                mma16816(acc[m][2 * p + 1], a, b + 2);
            }
        }
    // b-split 1: term a1b2 (a2b2 dropped, ~1e-8 rel; validated R10-R15)
#pragma unroll
    for (int p = 0; p < 6; p++) {
        const uint32_t* b = (const uint32_t*)&Bs1[p];
#pragma unroll
        for (int m = 0; m < 2; m++) {
            const uint32_t* a = (const uint32_t*)&Av[m * 2];
            mma16816(acc[m][2 * p],     a, b);
            mma16816(acc[m][2 * p + 1], a, b + 2);
        }
    }
}

// ---------------------------------------------------------------------------
// Head GEMM: 64 nodes x 384 cols per CTA; 8 warps (2 M x 4 N), tile 32x96.
// A arrives via a 4-stage per-thread cp.async smem pipeline (each thread
// copies exactly the fragments it later LDS.128-loads -> wait_group is the
// only sync; no barriers). B register double-buffered from L2 (proven R14).
// ---------------------------------------------------------------------------
__global__ void __launch_bounds__(NTHREAD, 1)
head_kernel(const float* __restrict__ b1, const float* __restrict__ lngamma,
            const float* __restrict__ lnbeta, const float* __restrict__ W2,
            const float* __restrict__ b2, float* __restrict__ logits)
{
    extern __shared__ char smx[];
    const uint32_t sb = smem_u32(smx);
    float* par = (float*)(smx + OFF_PAR);
    float* rs1 = (float*)(smx + OFF_RS1);
    float* rs2 = (float*)(smx + OFF_RS2);
    float* rt  = (float*)(smx + OFF_RT);

    const int tid  = threadIdx.x;
    const int wid  = tid >> 5;
    const int lane = tid & 31;
    const int wr   = wid & 1;            // M-warp (2), 32 rows each
    const int wc   = wid >> 1;           // N-warp (4), 96 cols each
    const int nb   = blockIdx.x;
    const int n0   = nb * MTILE;
    const float b2v = __ldg(b2);
    const uint32_t wsm = sb + OFF_STG + (uint32_t)wid * WARP_REGION;

    for (int i = tid; i < HID2; i += NTHREAD) {
        par[i]            = b1[i];
        par[HID2 + i]     = lngamma[i];
        par[2 * HID2 + i] = lnbeta[i];
        par[3 * HID2 + i] = W2[i];
    }

    const uint32_t wbase = (uint32_t)wc * 384u + (uint32_t)lane;

    float acc[2][12][4];
#pragma unroll
    for (int m = 0; m < 2; m++)
#pragma unroll
        for (int nt = 0; nt < 12; nt++)
#pragma unroll
            for (int j = 0; j < 4; j++) acc[m][nt][j] = 0.f;

    // ---- A pipeline prologue: stages for ks = 0,1,2 ----
    issueA(nb, wr, 0, 0, lane, wsm); CPCOMMIT();
    issueA(nb, wr, 1, 1, lane, wsm); CPCOMMIT();
    issueA(nb, wr, 2, 2, lane, wsm); CPCOMMIT();

    uint4 Afr[4], B[2][6];
    loadB0(B[0], 0, wbase);

    // ---- steady state: ks = 0..8 (issue ks+3, wait depth 3) ----
    for (int ks = 0; ks < 9; ks++) {
        issueA(nb, wr, ks + 3, (ks + 3) & 3, lane, wsm); CPCOMMIT();
        CPWAIT(3);
        ldsA(Afr, ks & 3, lane, wsm);
        loadB0(B[(ks + 1) & 1], ks + 1, wbase);
        doKstep(acc, Afr, B[ks & 1], ks, wbase);
    }
    // ---- tail: ks = 9,10,11 ----
    CPWAIT(2); ldsA(Afr, 1, lane, wsm);
    loadB0(B[0], 10, wbase);
    doKstep(acc, Afr, B[1], 9, wbase);
    CPWAIT(1); ldsA(Afr, 2, lane, wsm);
    loadB0(B[1], 11, wbase);
    doKstep(acc, Afr, B[0], 10, wbase);
    CPWAIT(0); ldsA(Afr, 3, lane, wsm);
    doKstep(acc, Afr, B[1], 11, wbase);

    __syncthreads();   // par visible (written before mainloop, first use below)

    // ---- epilogue: descale, +b1, LN stats, LN+ReLU+dot(W2) ----
    const int l4 = lane >> 2, lm = lane & 3;

#pragma unroll
    for (int m = 0; m < 2; m++)
#pragma unroll
        for (int hf = 0; hf < 2; hf++) {
            float s1 = 0.f, s2 = 0.f;
#pragma unroll
            for (int nt = 0; nt < 12; nt++) {
                const int cb = wc * 96 + nt * 8 + 2 * lm;
                float2 bv = *(const float2*)&par[cb];
                float v0 = acc[m][nt][2 * hf]     * DESCALE + bv.x;
                float v1 = acc[m][nt][2 * hf + 1] * DESCALE + bv.y;
                s1 += v0 + v1; s2 += v0 * v0 + v1 * v1;
            }
            s1 += __shfl_xor_sync(0xffffffffu, s1, 1);
            s1 += __shfl_xor_sync(0xffffffffu, s1, 2);
            s2 += __shfl_xor_sync(0xffffffffu, s2, 1);
            s2 += __shfl_xor_sync(0xffffffffu, s2, 2);
            if (lm == 0) {
                const int row = wr * 32 + m * 16 + hf * 8 + l4;
                rs1[row * 4 + wc] = s1;
                rs2[row * 4 + wc] = s2;
            }
        }
    __syncthreads();

#pragma unroll
    for (int m = 0; m < 2; m++)
#pragma unroll
        for (int hf = 0; hf < 2; hf++) {
            const int row = wr * 32 + m * 16 + hf * 8 + l4;
            const float S1 = rs1[row * 4] + rs1[row * 4 + 1] + rs1[row * 4 + 2] + rs1[row * 4 + 3];
            const float S2 = rs2[row * 4] + rs2[row * 4 + 1] + rs2[row * 4 + 2] + rs2[row * 4 + 3];
            const float mu  = S1 * (1.0f / HID2);
            const float var = S2 * (1.0f / HID2) - mu * mu;
            const float inv = rsqrtf(var + LN_EPS);
            float t = 0.f;
#pragma unroll
            for (int nt = 0; nt < 12; nt++) {
                const int cb = wc * 96 + nt * 8 + 2 * lm;
                float2 bv = *(const float2*)&par[cb];
                float2 gm = *(const float2*)&par[HID2 + cb];
                float2 bt = *(const float2*)&par[2 * HID2 + cb];
                float2 w2 = *(const float2*)&par[3 * HID2 + cb];
                float v0 = acc[m][nt][2 * hf]     * DESCALE + bv.x;
                float v1 = acc[m][nt][2 * hf + 1] * DESCALE + bv.y;
                float z0 = fmaxf((v0 - mu) * inv * gm.x + bt.x, 0.f);
                float z1 = fmaxf((v1 - mu) * inv * gm.y + bt.y, 0.f);
                t += z0 * w2.x + z1 * w2.y;
            }
            t += __shfl_xor_sync(0xffffffffu, t, 1);
            t += __shfl_xor_sync(0xffffffffu, t, 2);
            if (lm == 0) rt[row * 4 + wc] = t;
        }
    __syncthreads();
    if (tid < MTILE)
        logits[n0 + tid] = rt[tid * 4] + rt[tid * 4 + 1] + rt[tid * 4 + 2]
                         + rt[tid * 4 + 3] + b2v;
}

// ---------------------------------------------------------------------------
// Exact per-graph top-k (jax tie semantics). Writes kl = kept ? logit : +INF
// (single-float gather for edge) and pre-zeroes node_mask.
// ---------------------------------------------------------------------------
__global__ void __launch_bounds__(256)
topk_kernel(const float* __restrict__ logits, float* __restrict__ nm)
{
    __shared__ float sv[NPG];
    const int node = blockIdx.x * NPG + threadIdx.x;
    const int t = threadIdx.x;
    const float v = logits[node];
    sv[t] = v;
    nm[node] = 0.0f;
    __syncthreads();
    int rank = 0;
#pragma unroll 8
    for (int j = 0; j < NPG; j++) {
        const float u = sv[j];
        rank += (u > v) || (u == v && j < t);
    }
    d_kl[node] = (rank < KKEEP) ? v : F_INF;
}

// ---------------------------------------------------------------------------
// Edge masking + weights + node_mask (8 edges/thread, single-float gathers).
// s = kl[src] + kl[dst] is finite iff both endpoints kept.
// ---------------------------------------------------------------------------
__global__ void __launch_bounds__(256)
edge_kernel(const int* __restrict__ ei,
            float* __restrict__ em, float* __restrict__ ew,
            float* __restrict__ nm)
{
    const int t = blockIdx.x * 256 + threadIdx.x;    // NEDGE/8 threads
    const int4* ei4 = (const int4*)ei;
    const int4 sa = ei4[2 * t],              sb2 = ei4[2 * t + 1];
    const int4 da = ei4[NEDGE / 4 + 2 * t],  db  = ei4[NEDGE / 4 + 2 * t + 1];

    float s[8];
    s[0] = d_kl[sa.x] + d_kl[da.x];
    s[1] = d_kl[sa.y] + d_kl[da.y];
    s[2] = d_kl[sa.z] + d_kl[da.z];
    s[3] = d_kl[sa.w] + d_kl[da.w];
    s[4] = d_kl[sb2.x] + d_kl[db.x];
    s[5] = d_kl[sb2.y] + d_kl[db.y];
    s[6] = d_kl[sb2.z] + d_kl[db.z];
    s[7] = d_kl[sb2.w] + d_kl[db.w];

    float m[8], w[8];
#pragma unroll
    for (int j = 0; j < 8; j++) {
        m[j] = (s[j] < 3.0e38f) ? 1.0f : 0.0f;   // finite <=> both kept
        w[j] = (s[j] < 3.0e38f) ? s[j] : 0.0f;
    }

    ((float4*)em)[2 * t]     = make_float4(m[0], m[1], m[2], m[3]);
    ((float4*)em)[2 * t + 1] = make_float4(m[4], m[5], m[6], m[7]);
    ((float4*)ew)[2 * t]     = make_float4(w[0], w[1], w[2], w[3]);
    ((float4*)ew)[2 * t + 1] = make_float4(w[4], w[5], w[6], w[7]);

    if (m[0] != 0.f) { nm[sa.x] = 1.0f; nm[da.x] = 1.0f; }
    if (m[1] != 0.f) { nm[sa.y] = 1.0f; nm[da.y] = 1.0f; }
    if (m[2] != 0.f) { nm[sa.z] = 1.0f; nm[da.z] = 1.0f; }
    if (m[3] != 0.f) { nm[sa.w] = 1.0f; nm[da.w] = 1.0f; }
    if (m[4] != 0.f) { nm[sb2.x] = 1.0f; nm[db.x] = 1.0f; }
    if (m[5] != 0.f) { nm[sb2.y] = 1.0f; nm[db.y] = 1.0f; }
    if (m[6] != 0.f) { nm[sb2.z] = 1.0f; nm[db.z] = 1.0f; }
    if (m[7] != 0.f) { nm[sb2.w] = 1.0f; nm[db.w] = 1.0f; }
}

// ---------------------------------------------------------------------------
// Launch: outputs concatenated f32: edge_mask | edge_weight | logits | node_mask
// head_kernel is launch #4 (ncu capture slot).
// ---------------------------------------------------------------------------
extern "C" void kernel_launch(void* const* d_in, const int* in_sizes, int n_in,
                              void* d_out, int out_size)
{
    const float* h       = (const float*)d_in[0];
    const float* g       = (const float*)d_in[1];
    const int*   ei      = (const int*)  d_in[2];
    const float* W1      = (const float*)d_in[3];
    const float* b1      = (const float*)d_in[4];
    const float* lngamma = (const float*)d_in[5];
    const float* lnbeta  = (const float*)d_in[6];
    const float* W2      = (const float*)d_in[7];
    const float* b2      = (const float*)d_in[8];

    float* out = (float*)d_out;
    float* em = out;
    float* ew = out + (size_t)NEDGE;
    float* lg = out + 2 * (size_t)NEDGE;
    float* nm = lg + NODES;

    cudaFuncSetAttribute(asplit_kernel,
                         cudaFuncAttributeMaxDynamicSharedMemorySize, ASPLIT_SMEM);
    cudaFuncSetAttribute(head_kernel,
                         cudaFuncAttributeMaxDynamicSharedMemorySize, HEAD_SMEM);

    wsplit_kernel<<<576, 256>>>(W1);                        // #1
    asplit_kernel<<<NBA, 512, ASPLIT_SMEM>>>(h, g);         // #2
    dummy_kernel<<<1, 32>>>();                              // #3
    head_kernel<<<NB, NTHREAD, HEAD_SMEM>>>(                // #4  <- ncu slot
        b1, lngamma, lnbeta, W2, b2, lg);
    topk_kernel<<<BGRAPH, 256>>>(lg, nm);                   // #5
    edge_kernel<<<NEDGE / 2048, 256>>>(ei, em, ew, nm);     // #6
}